// round 16
// baseline (speedup 1.0000x reference)
#include <cuda_runtime.h>
#include <cuda_bf16.h>

// LearnableQuantization — gumbel-softmax over 17-bin log-sigmoid CDF grid.
// PRNG (verified R3): jax threefry2x32 partitionable; word i = y0^y1 of
// block (x0=0, x1=i), key (0,1).
//
// Fast path (|x| > 8.5a+14d, ~99.6%): softplus saturates, num_g constant per
// side; constants cancel in softmax -> per bin only r_g = rsqrt(-log2 U_g);
// bin 15 scaled by sqrt(6.2/3.2) above-grid. In-band lanes: unified path
// multiplies the same r_g by sqrt(num_g) (log2-vs-ln factor cancels).
//
// R16: 2 elements/thread (e and e+HALF; HALF%64==0 -> same alpha/dev, both
// streams coalesced) -> two independent cipher chains per thread. R13/R15
// showed issue stuck at 79% with 32 regs (ILP~1); this trades occupancy
// (launch_bounds 256,6 -> <=42 regs, 75% occ) for real per-thread ILP.

#define N_ELEMS  3145728            // 16*3*1024*8*8
#define HALF     (N_ELEMS / 2)      // 1572864, divisible by 64
#define NBLK2    (HALF / 256)       // 6144 blocks
#define RC_INV   (1.0f / 49152.0f)
#define RHO15    1.39194107f        // sqrt(6.2/3.2)

__device__ float    g_mean_accum[64];   // zero at load; finisher re-zeroes
__device__ unsigned g_done = 0;         // finisher resets for next replay
__device__ unsigned g_one = 1u;         // opaque: forces adds to IMAD
__device__ unsigned g_m26 = (1u << 26); // opaque: IMAD.WIDE rotate (r=26)

struct Cst { unsigned one, m26; };

// add on the fma pipe: IMAD(a, one, b)
__device__ __forceinline__ unsigned addi(unsigned a, unsigned one, unsigned b) {
    return a * one + b;
}

// threefry2x32-20, key (0,1), block (0, base+dg); returns y0^y1.
// dg is compile-time per unrolled call: x1 = base + (1+dg) in one IMAD.
// Round 1 degenerate (x0==0). Three r=26 rotates via u64 mul by opaque 2^26
// (IMAD.WIDE, fma) with (lo|hi)^x0 fused to one LOP3; rest SHF (alu).
__device__ __forceinline__ unsigned tf_bits(unsigned base, unsigned dg,
                                            const Cst& C) {
    const unsigned ks1 = 1u, ks2 = 0x1BD11BDBu;   // ks0 = 0
    unsigned one = C.one;
    unsigned x1 = addi(base, one, ks1 + dg);       // counter+key folded
    unsigned x0 = x1;                              // round 1: x0 = 0 + x1
    x1 = __funnelshift_l(x1, x1, 13) ^ x0;
#define RS(r) { x0 = addi(x0, one, x1); \
                x1 = __funnelshift_l(x1, x1, (r)) ^ x0; }
#define RW()  { x0 = addi(x0, one, x1); \
                unsigned long long t_ = (unsigned long long)x1 * C.m26; \
                x1 = (((unsigned)t_) | ((unsigned)(t_ >> 32))) ^ x0; }
    RS(15) RW() RS(6)
    x0 = addi(x0, one, ks1);  x1 = addi(x1, one, ks2 + 1u);
    RS(17) RS(29) RS(16) RS(24)
    x0 = addi(x0, one, ks2);  x1 = addi(x1, one, 2u);
    RS(13) RS(15) RW() RS(6)
    /* x0 += 0 */             x1 = addi(x1, one, ks1 + 3u);
    RS(17) RS(29) RS(16) RS(24)
    x0 = addi(x0, one, ks1);  x1 = addi(x1, one, ks2 + 4u);
    RS(13) RS(15) RW() RS(6)
    x0 = addi(x0, one, ks2);  x1 = addi(x1, one, 5u);
#undef RS
#undef RW
    return x0 ^ x1;
}

// r = rsqrt(max(32 - log2((float)bits), eps)) — proven rel_err 2.78e-4.
// FMNMX clamp is exact passthrough for m>0 — do NOT replace with an
// additive eps (R10: perturbs the tiny-m tail ~10%).
__device__ __forceinline__ float rbin(unsigned bits) {
    float f = __uint2float_rn(bits);
    float m = fmaxf(32.0f - __log2f(f), 1e-30f);
    return rsqrtf(m);
}

__device__ __forceinline__ float softplus_f(float s) {
    return fmaxf(s, 0.0f) + __logf(1.0f + __expf(-fabsf(s)));
}

// unified (in-band capable) path for one element; same r_g as lean path.
__device__ __forceinline__ float unified_elem(unsigned base, float xv,
                                              float a, float d, bool ib,
                                              const Cst& C) {
    float invd = 1.0f / d;
    float sp_prev = softplus_f((xv + 8.5f * a) * invd);
    float s = 0.0f, sg = 0.0f;
#pragma unroll 2
    for (unsigned g = 0; g < 16; ++g) {
        float r   = rbin(tf_bits(base, g, C));
        float bn  = (g == 15) ? 8.5f : ((float)(g + 1) - 8.5f);
        float sp  = softplus_f((xv - bn * a) * invd);
        float num = sp_prev - sp + 0.2f;   // > 0.199 always
        sp_prev = sp;
        float w;
        if (ib) w = r * sqrtf(num);
        else    w = (g == 15 && xv > 0.0f) ? r * RHO15 : r;
        s += w;
        sg = __fmaf_rn(w, (float)g - 8.5f, sg);
    }
    return a * __fdividef(sg, s);
}

__global__ void __launch_bounds__(256, 6) lq_main_kernel(
    const float* __restrict__ x,
    const float* __restrict__ alpha,
    const float* __restrict__ dev,
    float* __restrict__ out, int out_size)
{
    __shared__ float s_alpha[64], s_dev[64], s_inva[64], s_macc[64];
    __shared__ bool  s_last;
    int tid = threadIdx.x;
    if (tid < 64) {
        float a = alpha[tid];
        s_alpha[tid] = a;
        s_dev[tid]   = dev[tid];
        s_inva[tid]  = 1.0f / a;
        s_macc[tid]  = 0.0f;
    }
    __syncthreads();

    Cst C = { g_one, g_m26 };

    int e1 = blockIdx.x * 256 + tid;   // [0, HALF)
    int e2 = e1 + HALF;                // same rc (HALF % 64 == 0)
    int rc = e1 & 63;
    float a  = s_alpha[rc];
    float d  = s_dev[rc];
    float x1 = x[e1];
    float x2 = x[e2];

    atomicAdd(&s_macc[rc], fabsf(x1 * s_inva[rc]) + fabsf(x2 * s_inva[rc]));

    unsigned b1 = (unsigned)e1 * 16u;
    unsigned b2 = (unsigned)e2 * 16u;
    float thr = __fmaf_rn(14.0f, d, 8.5f * a);
    bool ib1 = fabsf(x1) <= thr;
    bool ib2 = fabsf(x2) <= thr;

    if (!__any_sync(0xffffffffu, ib1 || ib2)) {
        // ---- dual lean path: two independent cipher chains per bin ----
        float s1 = 0.0f, sg1 = 0.0f, s2 = 0.0f, sg2 = 0.0f;
#pragma unroll
        for (unsigned g = 0; g < 15; ++g) {
            float ra = rbin(tf_bits(b1, g, C));
            float rb = rbin(tf_bits(b2, g, C));
            s1 += ra;  sg1 = __fmaf_rn(ra, (float)g - 8.5f, sg1);
            s2 += rb;  sg2 = __fmaf_rn(rb, (float)g - 8.5f, sg2);
        }
        float ra = rbin(tf_bits(b1, 15u, C));
        float rb = rbin(tf_bits(b2, 15u, C));
        float wa = (x1 > 0.0f) ? ra * RHO15 : ra;
        float wb = (x2 > 0.0f) ? rb * RHO15 : rb;
        s1 += wa;  sg1 = __fmaf_rn(wa, 6.5f, sg1);
        s2 += wb;  sg2 = __fmaf_rn(wb, 6.5f, sg2);
        out[e1] = a * __fdividef(sg1, s1);
        out[e2] = a * __fdividef(sg2, s2);
    } else {
        // ---- unified path (rare): exact softplus chain, same r_g ----
        out[e1] = unified_elem(b1, x1, a, d, ib1, C);
        out[e2] = unified_elem(b2, x2, a, d, ib2, C);
    }

    // ---- mean reduction + fused finisher (last block publishes) ----
    __syncthreads();
    if (tid < 64) atomicAdd(&g_mean_accum[tid], s_macc[tid]);
    __syncthreads();
    if (tid == 0) {
        __threadfence();
        s_last = (atomicAdd(&g_done, 1u) == (unsigned)(NBLK2 - 1));
    }
    __syncthreads();
    if (s_last) {
        if (tid < 64) {
            float v = atomicAdd(&g_mean_accum[tid], 0.0f);  // coherent read
            g_mean_accum[tid] = 0.0f;          // clean for next graph replay
            if (out_size > N_ELEMS + tid)
                out[N_ELEMS + tid] = v * RC_INV;
        }
        if (tid == 0) {
            g_done = 0;                        // clean for next graph replay
            if (out_size > N_ELEMS + 64)
                out[N_ELEMS + 64] = 0.0f;      // nzeros
        }
    }
}

extern "C" void kernel_launch(void* const* d_in, const int* in_sizes, int n_in,
                              void* d_out, int out_size) {
    const float* x     = (const float*)d_in[0];
    const float* alpha = (const float*)d_in[1];
    const float* dev   = (const float*)d_in[2];
    float* out = (float*)d_out;

    lq_main_kernel<<<NBLK2, 256>>>(x, alpha, dev, out, out_size);
}